// round 16
// baseline (speedup 1.0000x reference)
#include <cuda_runtime.h>
#include <cuda_bf16.h>

#define NMAX   100000
#define EMAX   640000
#define LATDIM 128
#define VEC    32          // float4 per row
#define SCAN_B 1024
#define MAXBLK 128         // >= number of scan blocks (98)
#define SPMM_TPB 128       // proven optimum (256 worse, 64 worse)

// ---- scratch (__device__ globals; zero-initialized at module load) ---------
__device__ float g_bufA[(size_t)NMAX * LATDIM];
__device__ float g_bufB[(size_t)NMAX * LATDIM];
__device__ int   g_cnt[NMAX];          // per-row degree (zero at entry, re-zeroed by scatter)
__device__ int   g_rowstart[NMAX];     // block-local exclusive scan
__device__ uint2 g_rowmeta[NMAX];      // {absolute base, degree} per row
__device__ int   g_bsum[MAXBLK];       // per-scan-block totals
__device__ int   g_bpref[MAXBLK];      // exclusive scan of totals
__device__ int   g_rank[EMAX];         // within-row rank of each edge
__device__ uint2 g_edges[EMAX];        // row-sorted {col, val bits}
__device__ int   g_scan_done;          // scan election counter (reset by scatter)

// ---------------------------------------------------------------------------
// LN body: one warp per node (1024-thread blocks => 32 nodes/block)
// ---------------------------------------------------------------------------
__device__ __forceinline__ void ln_node(const float* __restrict__ in,
                                        float* __restrict__ out,
                                        int node, int lane) {
    float4 v = __ldg(reinterpret_cast<const float4*>(in) + (size_t)node * VEC + lane);

    float s  = v.x + v.y + v.z + v.w;
    float ss = v.x * v.x + v.y * v.y + v.z * v.z + v.w * v.w;
    #pragma unroll
    for (int o = 16; o > 0; o >>= 1) {
        s  += __shfl_xor_sync(0xFFFFFFFFu, s,  o);
        ss += __shfl_xor_sync(0xFFFFFFFFu, ss, o);
    }
    float mu  = s * (1.0f / LATDIM);
    float var = ss * (1.0f / LATDIM) - mu * mu;
    float inv = rsqrtf(var + 1e-5f);

    v.x = (v.x - mu) * inv; v.y = (v.y - mu) * inv;
    v.z = (v.z - mu) * inv; v.w = (v.w - mu) * inv;

    reinterpret_cast<float4*>(out)[(size_t)node * VEC + lane] = v;
}

// ---------------------------------------------------------------------------
// k1: hist blocks [0, hist_blocks) + LN chunk blocks after.
// ---------------------------------------------------------------------------
__global__ void __launch_bounds__(SCAN_B)
hist_ln_kernel(const int* __restrict__ row,
               const float* __restrict__ ln_in, float* __restrict__ ln_out,
               int n_edges, int n_nodes, int hist_blocks, int ln_node_base) {
    int t = threadIdx.x, lane = t & 31, wid = t >> 5;

    if (blockIdx.x >= hist_blocks) {
        int node = ln_node_base + (blockIdx.x - hist_blocks) * (SCAN_B / 32) + wid;
        if (node < n_nodes) ln_node(ln_in, ln_out, node, lane);
        return;
    }

    int e = blockIdx.x * SCAN_B + t;
    if (e < n_edges)
        g_rank[e] = atomicAdd(&g_cnt[row[e]], 1);
}

// ---------------------------------------------------------------------------
// k2: scan blocks [0, scan_blocks) + LN chunk blocks after.
// ---------------------------------------------------------------------------
__global__ void __launch_bounds__(SCAN_B)
scan_ln_kernel(const float* __restrict__ ln_in, float* __restrict__ ln_out,
               int n_nodes, int scan_blocks, int ln_node_base) {
    int t = threadIdx.x, lane = t & 31, wid = t >> 5;

    if (blockIdx.x >= scan_blocks) {
        int node = ln_node_base + (blockIdx.x - scan_blocks) * (SCAN_B / 32) + wid;
        if (node < n_nodes) ln_node(ln_in, ln_out, node, lane);
        return;
    }

    __shared__ int wsum[32];
    __shared__ int wsum2[4];
    __shared__ bool s_last;
    int i = blockIdx.x * SCAN_B + t;
    int v = (i < n_nodes) ? g_cnt[i] : 0;

    int x = v;
    #pragma unroll
    for (int o = 1; o < 32; o <<= 1) {
        int y = __shfl_up_sync(0xFFFFFFFFu, x, o);
        if (lane >= o) x += y;
    }
    if (lane == 31) wsum[wid] = x;
    __syncthreads();
    if (wid == 0) {
        int s = wsum[lane];
        #pragma unroll
        for (int o = 1; o < 32; o <<= 1) {
            int y = __shfl_up_sync(0xFFFFFFFFu, s, o);
            if (lane >= o) s += y;
        }
        wsum[lane] = s;
    }
    __syncthreads();
    int incl = x + (wid ? wsum[wid - 1] : 0);
    if (i < n_nodes) g_rowstart[i] = incl - v;
    if (t == SCAN_B - 1) g_bsum[blockIdx.x] = incl;

    __threadfence();
    if (t == 0)
        s_last = (atomicAdd(&g_scan_done, 1) == scan_blocks - 1);
    __syncthreads();

    if (s_last) {
        int bv = 0, bx = 0;
        if (t < MAXBLK) {
            bv = (t < scan_blocks) ? g_bsum[t] : 0;
            bx = bv;
            #pragma unroll
            for (int o = 1; o < 32; o <<= 1) {
                int y = __shfl_up_sync(0xFFFFFFFFu, bx, o);
                if (lane >= o) bx += y;
            }
            if (lane == 31) wsum2[wid] = bx;
        }
        __syncthreads();
        if (t < MAXBLK) {
            int pre = 0;
            #pragma unroll
            for (int w = 0; w < 4; ++w) if (w < wid) pre += wsum2[w];
            g_bpref[t] = bx + pre - bv;
        }
    }
}

// ---------------------------------------------------------------------------
// k3: scatter blocks [0, scatter_blocks) + LN chunk blocks after.
// scatter: atomic-free (rank-based). First n_nodes threads also:
//   - materialize {absolute base, degree} into g_rowmeta (one 8B spmm load),
//   - re-zero g_cnt, reset g_scan_done (recycled for next graph replay).
// ---------------------------------------------------------------------------
__global__ void __launch_bounds__(SCAN_B)
scatter_ln_kernel(const int* __restrict__ row,
                  const int* __restrict__ col,
                  const float* __restrict__ val,
                  const float* __restrict__ ln_in, float* __restrict__ ln_out,
                  int n_edges, int n_nodes, int scatter_blocks, int ln_node_base) {
    int t = threadIdx.x, lane = t & 31, wid = t >> 5;

    if (blockIdx.x >= scatter_blocks) {
        int node = ln_node_base + (blockIdx.x - scatter_blocks) * (SCAN_B / 32) + wid;
        if (node < n_nodes) ln_node(ln_in, ln_out, node, lane);
        return;
    }

    int e = blockIdx.x * SCAN_B + t;

    if (e == 0) g_scan_done = 0;                 // recycle election counter
    if (e < n_nodes) {
        int d = g_cnt[e];
        g_rowmeta[e] = make_uint2((unsigned)(g_rowstart[e] + g_bpref[e >> 10]),
                                  (unsigned)d);
        g_cnt[e] = 0;                            // recycle degree counters
    }

    if (e >= n_edges) return;

    int   r  = __ldg(row + e);      // independent loads up front
    int   c  = __ldg(col + e);
    float v  = __ldg(val + e);
    int   rk = __ldg(&g_rank[e]);

    int base = __ldg(&g_rowstart[r]) + __ldg(&g_bpref[r >> 10]);
    g_edges[base + rk] = make_uint2((unsigned)c, __float_as_uint(v));
}

// ---------------------------------------------------------------------------
// SpMM (round-4 proven inner structure, frozen): 1 warp per row, lane owns
// one float4, 128-thread blocks (round-13 optimum). Prologue: ONE 8B
// broadcast load of {base, deg}. Fast path for deg <= 32 (≈100% of rows
// under Poisson(6.4)) removes outer-loop bound arithmetic.
// FINAL==0 : y = acc                    (layers 1,2 — zero `out` traffic)
// FINAL==1 : out = acc + y1[r] + x[r]   (layer 3; x row == y2; streaming hints)
// ---------------------------------------------------------------------------
template <int FINAL>
__global__ void __launch_bounds__(SPMM_TPB)
spmm_kernel(const float* __restrict__ x,
            float* __restrict__ y,
            const float* __restrict__ y1,
            float* __restrict__ out,
            int n_nodes) {
    int r = (blockIdx.x * blockDim.x + threadIdx.x) >> 5;
    if (r >= n_nodes) return;
    int lane = threadIdx.x & 31;

    uint2 meta = __ldg(&g_rowmeta[r]);   // one 8B load: {base, deg}
    int base = (int)meta.x;
    int deg  = (int)meta.y;

    const float4* x4 = reinterpret_cast<const float4*>(x);
    float4 acc = make_float4(0.f, 0.f, 0.f, 0.f);

    if (deg <= 32) {
        // ---- fast path: single batch, no outer loop ----
        uint2 ev = make_uint2(0u, 0u);
        if (lane < deg) ev = __ldg(&g_edges[base + lane]);     // coalesced meta
        #pragma unroll 4
        for (int k = 0; k < deg; ++k) {
            int   c = __shfl_sync(0xFFFFFFFFu, (int)ev.x, k);
            float v = __uint_as_float(__shfl_sync(0xFFFFFFFFu, (int)ev.y, k));
            float4 xv = __ldg(x4 + (size_t)c * VEC + lane);
            acc.x = fmaf(v, xv.x, acc.x);
            acc.y = fmaf(v, xv.y, acc.y);
            acc.z = fmaf(v, xv.z, acc.z);
            acc.w = fmaf(v, xv.w, acc.w);
        }
    } else {
        for (int s = 0; s < deg; s += 32) {
            int m = deg - s; if (m > 32) m = 32;
            uint2 ev = make_uint2(0u, 0u);
            if (lane < m) ev = __ldg(&g_edges[base + s + lane]);
            #pragma unroll 4
            for (int k = 0; k < m; ++k) {
                int   c = __shfl_sync(0xFFFFFFFFu, (int)ev.x, k);
                float v = __uint_as_float(__shfl_sync(0xFFFFFFFFu, (int)ev.y, k));
                float4 xv = __ldg(x4 + (size_t)c * VEC + lane);
                acc.x = fmaf(v, xv.x, acc.x);
                acc.y = fmaf(v, xv.y, acc.y);
                acc.z = fmaf(v, xv.z, acc.z);
                acc.w = fmaf(v, xv.w, acc.w);
            }
        }
    }

    size_t oi = (size_t)r * VEC + lane;
    if (FINAL == 0) {
        reinterpret_cast<float4*>(y)[oi] = acc;   // stays L2-hot for next layer
    } else {
        float4 a = __ldcs(reinterpret_cast<const float4*>(y1) + oi);  // evict-first
        float4 b = __ldg(x4 + oi);                                    // y2 row: L2-hot
        acc.x += a.x + b.x; acc.y += a.y + b.y;
        acc.z += a.z + b.z; acc.w += a.w + b.w;
        __stcs(reinterpret_cast<float4*>(out) + oi, acc);             // streaming
    }
}

// ---------------------------------------------------------------------------
// Launcher
// ---------------------------------------------------------------------------
extern "C" void kernel_launch(void* const* d_in, const int* in_sizes, int n_in,
                              void* d_out, int out_size) {
    const float* embeds  = (const float*)d_in[0];
    const int*   adj_row = (const int*)d_in[1];
    const int*   adj_col = (const int*)d_in[2];
    const float* adj_val = (const float*)d_in[3];

    int n_nodes = in_sizes[0] / LATDIM;
    int n_edges = in_sizes[1];

    float* bufA = nullptr;
    float* bufB = nullptr;
    cudaGetSymbolAddress((void**)&bufA, g_bufA);
    cudaGetSymbolAddress((void**)&bufB, g_bufB);
    float* out = (float*)d_out;

    int spmm_blocks    = (n_nodes * 32 + SPMM_TPB - 1) / SPMM_TPB;  // 1 warp/node
    int scan_blocks    = (n_nodes + SCAN_B - 1) / SCAN_B;           // 98
    int hist_blocks    = (n_edges + SCAN_B - 1) / SCAN_B;           // 625
    int scatter_blocks = (n_edges + SCAN_B - 1) / SCAN_B;           // 625

    // LN split across the three build kernels: 30% hist / 20% scan / 50% scatter
    // (round-13 proven split)
    int nodes_per_blk = SCAN_B / 32;                                // 32 nodes/block
    int ln0_nodes = (int)((long long)n_nodes * 30 / 100);           // with hist
    int ln1_nodes = (int)((long long)n_nodes * 20 / 100);           // with scan
    int ln0_blocks = (ln0_nodes + nodes_per_blk - 1) / nodes_per_blk;
    ln0_nodes = ln0_blocks * nodes_per_blk;
    int ln1_blocks = (ln1_nodes + nodes_per_blk - 1) / nodes_per_blk;
    ln1_nodes = ln1_blocks * nodes_per_blk;
    if (ln0_nodes + ln1_nodes > n_nodes) {
        ln1_nodes  = n_nodes - ln0_nodes;
        ln1_blocks = (ln1_nodes + nodes_per_blk - 1) / nodes_per_blk;
    }
    int ln2_base   = ln0_nodes + ln1_nodes;                         // with scatter
    int ln2_nodes  = n_nodes - ln2_base;
    int ln2_blocks = (ln2_nodes + nodes_per_blk - 1) / nodes_per_blk;

    // 1) hist  ∥  LN part 0   (g_cnt arrives zeroed — module init / recycled)
    hist_ln_kernel<<<hist_blocks + ln0_blocks, SCAN_B>>>(
        adj_row, embeds, bufA, n_edges, n_nodes, hist_blocks, 0);
    // 2) scan  ∥  LN part 1
    scan_ln_kernel<<<scan_blocks + ln1_blocks, SCAN_B>>>(
        embeds, bufA, n_nodes, scan_blocks, ln0_nodes);
    // 3) scatter + rowmeta fixup + counter recycle  ∥  LN part 2
    scatter_ln_kernel<<<scatter_blocks + ln2_blocks, SCAN_B>>>(
        adj_row, adj_col, adj_val, embeds, bufA,
        n_edges, n_nodes, scatter_blocks, ln2_base);

    // 4) Layer 1: y1 = A * x0          (bufA -> bufB)
    spmm_kernel<0><<<spmm_blocks, SPMM_TPB>>>(bufA, bufB, nullptr, nullptr, n_nodes);
    // 5) Layer 2: y2 = A * y1          (bufB -> bufA)
    spmm_kernel<0><<<spmm_blocks, SPMM_TPB>>>(bufB, bufA, nullptr, nullptr, n_nodes);
    // 6) Layer 3: out = A*y2 + y1 + y2 (gather bufA; add bufB + bufA rows)
    spmm_kernel<1><<<spmm_blocks, SPMM_TPB>>>(bufA, nullptr, bufB, out, n_nodes);
}

// round 17
// speedup vs baseline: 1.0269x; 1.0269x over previous
#include <cuda_runtime.h>
#include <cuda_bf16.h>

#define NMAX   100000
#define EMAX   640000
#define LATDIM 128
#define VEC    32          // float4 per row
#define SCAN_B 1024
#define MAXBLK 128         // >= number of scan blocks (98)
#define SPMM_TPB 128       // proven optimum (256 worse, 64 worse)

// ---- scratch (__device__ globals; zero-initialized at module load) ---------
__device__ float g_bufA[(size_t)NMAX * LATDIM];
__device__ float g_bufB[(size_t)NMAX * LATDIM];
__device__ int   g_cnt[NMAX];          // per-row degree (zero at entry, re-zeroed by scatter)
__device__ int   g_rowstart[NMAX];     // block-local exclusive scan
__device__ int   g_rowabs[NMAX + 1];   // ABSOLUTE row starts
__device__ int   g_bsum[MAXBLK];       // per-scan-block totals
__device__ int   g_bpref[MAXBLK];      // exclusive scan of totals
__device__ int   g_rank[EMAX];         // within-row rank of each edge
__device__ uint2 g_edges[EMAX];        // row-sorted {col, val bits}
__device__ int   g_scan_done;          // scan election counter (reset by scatter)

// ---------------------------------------------------------------------------
// LN body: one warp per node (1024-thread blocks => 32 nodes/block)
// ---------------------------------------------------------------------------
__device__ __forceinline__ void ln_node(const float* __restrict__ in,
                                        float* __restrict__ out,
                                        int node, int lane) {
    float4 v = __ldg(reinterpret_cast<const float4*>(in) + (size_t)node * VEC + lane);

    float s  = v.x + v.y + v.z + v.w;
    float ss = v.x * v.x + v.y * v.y + v.z * v.z + v.w * v.w;
    #pragma unroll
    for (int o = 16; o > 0; o >>= 1) {
        s  += __shfl_xor_sync(0xFFFFFFFFu, s,  o);
        ss += __shfl_xor_sync(0xFFFFFFFFu, ss, o);
    }
    float mu  = s * (1.0f / LATDIM);
    float var = ss * (1.0f / LATDIM) - mu * mu;
    float inv = rsqrtf(var + 1e-5f);

    v.x = (v.x - mu) * inv; v.y = (v.y - mu) * inv;
    v.z = (v.z - mu) * inv; v.w = (v.w - mu) * inv;

    reinterpret_cast<float4*>(out)[(size_t)node * VEC + lane] = v;
}

// ---------------------------------------------------------------------------
// k1: hist blocks [0, hist_blocks) + LN chunk blocks after.
// ---------------------------------------------------------------------------
__global__ void __launch_bounds__(SCAN_B)
hist_ln_kernel(const int* __restrict__ row,
               const float* __restrict__ ln_in, float* __restrict__ ln_out,
               int n_edges, int n_nodes, int hist_blocks, int ln_node_base) {
    int t = threadIdx.x, lane = t & 31, wid = t >> 5;

    if (blockIdx.x >= hist_blocks) {
        int node = ln_node_base + (blockIdx.x - hist_blocks) * (SCAN_B / 32) + wid;
        if (node < n_nodes) ln_node(ln_in, ln_out, node, lane);
        return;
    }

    int e = blockIdx.x * SCAN_B + t;
    if (e < n_edges)
        g_rank[e] = atomicAdd(&g_cnt[row[e]], 1);
}

// ---------------------------------------------------------------------------
// k2: scan blocks [0, scan_blocks) + LN chunk blocks after.
// ---------------------------------------------------------------------------
__global__ void __launch_bounds__(SCAN_B)
scan_ln_kernel(const float* __restrict__ ln_in, float* __restrict__ ln_out,
               int n_nodes, int scan_blocks, int ln_node_base) {
    int t = threadIdx.x, lane = t & 31, wid = t >> 5;

    if (blockIdx.x >= scan_blocks) {
        int node = ln_node_base + (blockIdx.x - scan_blocks) * (SCAN_B / 32) + wid;
        if (node < n_nodes) ln_node(ln_in, ln_out, node, lane);
        return;
    }

    __shared__ int wsum[32];
    __shared__ int wsum2[4];
    __shared__ bool s_last;
    int i = blockIdx.x * SCAN_B + t;
    int v = (i < n_nodes) ? g_cnt[i] : 0;

    int x = v;
    #pragma unroll
    for (int o = 1; o < 32; o <<= 1) {
        int y = __shfl_up_sync(0xFFFFFFFFu, x, o);
        if (lane >= o) x += y;
    }
    if (lane == 31) wsum[wid] = x;
    __syncthreads();
    if (wid == 0) {
        int s = wsum[lane];
        #pragma unroll
        for (int o = 1; o < 32; o <<= 1) {
            int y = __shfl_up_sync(0xFFFFFFFFu, s, o);
            if (lane >= o) s += y;
        }
        wsum[lane] = s;
    }
    __syncthreads();
    int incl = x + (wid ? wsum[wid - 1] : 0);
    if (i < n_nodes) g_rowstart[i] = incl - v;
    if (t == SCAN_B - 1) g_bsum[blockIdx.x] = incl;

    __threadfence();
    if (t == 0)
        s_last = (atomicAdd(&g_scan_done, 1) == scan_blocks - 1);
    __syncthreads();

    if (s_last) {
        int bv = 0, bx = 0;
        if (t < MAXBLK) {
            bv = (t < scan_blocks) ? g_bsum[t] : 0;
            bx = bv;
            #pragma unroll
            for (int o = 1; o < 32; o <<= 1) {
                int y = __shfl_up_sync(0xFFFFFFFFu, bx, o);
                if (lane >= o) bx += y;
            }
            if (lane == 31) wsum2[wid] = bx;
        }
        __syncthreads();
        if (t < MAXBLK) {
            int pre = 0;
            #pragma unroll
            for (int w = 0; w < 4; ++w) if (w < wid) pre += wsum2[w];
            g_bpref[t] = bx + pre - bv;
        }
    }
}

// ---------------------------------------------------------------------------
// k3: scatter blocks [0, scatter_blocks) + LN chunk blocks after.
// scatter: atomic-free (rank-based). First n_nodes+1 threads also:
//   - materialize ABSOLUTE rowstarts into g_rowabs,
//   - re-zero g_cnt, reset g_scan_done (recycled for next graph replay).
// ---------------------------------------------------------------------------
__global__ void __launch_bounds__(SCAN_B)
scatter_ln_kernel(const int* __restrict__ row,
                  const int* __restrict__ col,
                  const float* __restrict__ val,
                  const float* __restrict__ ln_in, float* __restrict__ ln_out,
                  int n_edges, int n_nodes, int scatter_blocks, int ln_node_base) {
    int t = threadIdx.x, lane = t & 31, wid = t >> 5;

    if (blockIdx.x >= scatter_blocks) {
        int node = ln_node_base + (blockIdx.x - scatter_blocks) * (SCAN_B / 32) + wid;
        if (node < n_nodes) ln_node(ln_in, ln_out, node, lane);
        return;
    }

    int e = blockIdx.x * SCAN_B + t;

    if (e == 0) g_scan_done = 0;                 // recycle election counter
    if (e <= n_nodes) {
        g_rowabs[e] = (e < n_nodes) ? (g_rowstart[e] + g_bpref[e >> 10]) : n_edges;
        if (e < n_nodes) g_cnt[e] = 0;           // recycle degree counters
    }

    if (e >= n_edges) return;

    int   r  = __ldg(row + e);      // independent loads up front
    int   c  = __ldg(col + e);
    float v  = __ldg(val + e);
    int   rk = __ldg(&g_rank[e]);

    int base = __ldg(&g_rowstart[r]) + __ldg(&g_bpref[r >> 10]);
    g_edges[base + rk] = make_uint2((unsigned)c, __float_as_uint(v));
}

// ---------------------------------------------------------------------------
// SpMM (round-4 proven inner structure, frozen): 1 warp per row, lane owns
// one float4, 128-thread blocks (round-13 measured optimum). Single code
// path (32 regs -> 81% occupancy; duplicated paths cost occupancy, r16).
// FINAL==0 : y = acc                    (layers 1,2 — zero `out` traffic)
// FINAL==1 : out = acc + y1[r] + x[r]   (layer 3; x row == y2; streaming hints)
// ---------------------------------------------------------------------------
template <int FINAL>
__global__ void __launch_bounds__(SPMM_TPB)
spmm_kernel(const float* __restrict__ x,
            float* __restrict__ y,
            const float* __restrict__ y1,
            float* __restrict__ out,
            int n_nodes) {
    int r = (blockIdx.x * blockDim.x + threadIdx.x) >> 5;
    if (r >= n_nodes) return;
    int lane = threadIdx.x & 31;

    int base = __ldg(&g_rowabs[r]);
    int deg  = __ldg(&g_rowabs[r + 1]) - base;

    const float4* x4 = reinterpret_cast<const float4*>(x);
    float4 acc = make_float4(0.f, 0.f, 0.f, 0.f);

    for (int s = 0; s < deg; s += 32) {
        int m = deg - s; if (m > 32) m = 32;
        uint2 ev = make_uint2(0u, 0u);
        if (lane < m) ev = __ldg(&g_edges[base + s + lane]);   // coalesced meta
        #pragma unroll 4
        for (int k = 0; k < m; ++k) {
            int   c = __shfl_sync(0xFFFFFFFFu, (int)ev.x, k);
            float v = __uint_as_float(__shfl_sync(0xFFFFFFFFu, (int)ev.y, k));
            float4 xv = __ldg(x4 + (size_t)c * VEC + lane);
            acc.x = fmaf(v, xv.x, acc.x);
            acc.y = fmaf(v, xv.y, acc.y);
            acc.z = fmaf(v, xv.z, acc.z);
            acc.w = fmaf(v, xv.w, acc.w);
        }
    }

    size_t oi = (size_t)r * VEC + lane;
    if (FINAL == 0) {
        reinterpret_cast<float4*>(y)[oi] = acc;   // stays L2-hot for next layer
    } else {
        float4 a = __ldcs(reinterpret_cast<const float4*>(y1) + oi);  // evict-first
        float4 b = __ldg(x4 + oi);                                    // y2 row: L2-hot
        acc.x += a.x + b.x; acc.y += a.y + b.y;
        acc.z += a.z + b.z; acc.w += a.w + b.w;
        __stcs(reinterpret_cast<float4*>(out) + oi, acc);             // streaming
    }
}

// ---------------------------------------------------------------------------
// Launcher
// ---------------------------------------------------------------------------
extern "C" void kernel_launch(void* const* d_in, const int* in_sizes, int n_in,
                              void* d_out, int out_size) {
    const float* embeds  = (const float*)d_in[0];
    const int*   adj_row = (const int*)d_in[1];
    const int*   adj_col = (const int*)d_in[2];
    const float* adj_val = (const float*)d_in[3];

    int n_nodes = in_sizes[0] / LATDIM;
    int n_edges = in_sizes[1];

    float* bufA = nullptr;
    float* bufB = nullptr;
    cudaGetSymbolAddress((void**)&bufA, g_bufA);
    cudaGetSymbolAddress((void**)&bufB, g_bufB);
    float* out = (float*)d_out;

    int spmm_blocks    = (n_nodes * 32 + SPMM_TPB - 1) / SPMM_TPB;  // 1 warp/node
    int scan_blocks    = (n_nodes + SCAN_B - 1) / SCAN_B;           // 98
    int hist_blocks    = (n_edges + SCAN_B - 1) / SCAN_B;           // 625
    int scatter_blocks = (n_edges + SCAN_B - 1) / SCAN_B;           // 625

    // LN split across the three build kernels: 30% hist / 20% scan / 50% scatter
    int nodes_per_blk = SCAN_B / 32;                                // 32 nodes/block
    int ln0_nodes = (int)((long long)n_nodes * 30 / 100);           // with hist
    int ln1_nodes = (int)((long long)n_nodes * 20 / 100);           // with scan
    int ln0_blocks = (ln0_nodes + nodes_per_blk - 1) / nodes_per_blk;
    ln0_nodes = ln0_blocks * nodes_per_blk;
    int ln1_blocks = (ln1_nodes + nodes_per_blk - 1) / nodes_per_blk;
    ln1_nodes = ln1_blocks * nodes_per_blk;
    if (ln0_nodes + ln1_nodes > n_nodes) {
        ln1_nodes  = n_nodes - ln0_nodes;
        ln1_blocks = (ln1_nodes + nodes_per_blk - 1) / nodes_per_blk;
    }
    int ln2_base   = ln0_nodes + ln1_nodes;                         // with scatter
    int ln2_nodes  = n_nodes - ln2_base;
    int ln2_blocks = (ln2_nodes + nodes_per_blk - 1) / nodes_per_blk;

    // 1) hist  ∥  LN part 0   (g_cnt arrives zeroed — module init / recycled)
    hist_ln_kernel<<<hist_blocks + ln0_blocks, SCAN_B>>>(
        adj_row, embeds, bufA, n_edges, n_nodes, hist_blocks, 0);
    // 2) scan  ∥  LN part 1
    scan_ln_kernel<<<scan_blocks + ln1_blocks, SCAN_B>>>(
        embeds, bufA, n_nodes, scan_blocks, ln0_nodes);
    // 3) scatter + rowabs fixup + counter recycle  ∥  LN part 2
    scatter_ln_kernel<<<scatter_blocks + ln2_blocks, SCAN_B>>>(
        adj_row, adj_col, adj_val, embeds, bufA,
        n_edges, n_nodes, scatter_blocks, ln2_base);

    // 4) Layer 1: y1 = A * x0          (bufA -> bufB)
    spmm_kernel<0><<<spmm_blocks, SPMM_TPB>>>(bufA, bufB, nullptr, nullptr, n_nodes);
    // 5) Layer 2: y2 = A * y1          (bufB -> bufA)
    spmm_kernel<0><<<spmm_blocks, SPMM_TPB>>>(bufB, bufA, nullptr, nullptr, n_nodes);
    // 6) Layer 3: out = A*y2 + y1 + y2 (gather bufA; add bufB + bufA rows)
    spmm_kernel<1><<<spmm_blocks, SPMM_TPB>>>(bufA, nullptr, bufB, out, n_nodes);
}